// round 15
// baseline (speedup 1.0000x reference)
#include <cuda_runtime.h>
#include <math.h>
#include <stdint.h>

// Problem constants
constexpr int Bb = 2;
constexpr int Ss = 2048;
constexpr int Dd = 768;
constexpr int Hh = 12;
constexpr int DHd = 64;
constexpr int WIN = 128;

// Scratch (device globals; no allocation allowed)
// Q/K/V/Z are HEAD-MAJOR: [b][h][s][d], plane stride Ss*64 = 131072 = 1<<17
__device__ __align__(16) float g_Q[Bb * Hh * Ss * DHd];
__device__ __align__(16) float g_K[Bb * Hh * Ss * DHd];
__device__ __align__(16) float g_V[Bb * Hh * Ss * DHd];
__device__ __align__(16) float g_Z[Bb * Hh * Ss * DHd];
// tf32-pre-rounded operands
__device__ __align__(16) float g_Aq[Bb * Ss * Dd];
__device__ __align__(16) float g_Ak[Bb * Ss * Dd];
__device__ __align__(16) float g_Av[Bb * Ss * Dd];
__device__ __align__(16) float g_Wq[Hh * Dd * DHd];
__device__ __align__(16) float g_Wk[Hh * Dd * DHd];
__device__ __align__(16) float g_Wv[Hh * Dd * DHd];
__device__ __align__(16) float g_Wo[Hh * DHd * Dd];
// rotary sin/cos table: [pos][freq] -> (sin, cos)
__device__ __align__(16) float2 g_T[Ss * 32];

__device__ __forceinline__ uint32_t f2tf32(float x) {
    uint32_t u;
    asm("cvt.rna.tf32.f32 %0, %1;" : "=r"(u) : "f"(x));
    return u;
}
__device__ __forceinline__ float round_tf32(float x) {
    return __uint_as_float(f2tf32(x));
}
__device__ __forceinline__ void cpa16(uint32_t dst, const void* src) {
    asm volatile("cp.async.cg.shared.global [%0], [%1], 16;"
                 :: "r"(dst), "l"(src) : "memory");
}
// zero-fill variant: src-size 0 -> writes 16 zero bytes
__device__ __forceinline__ void cpa16p(uint32_t dst, const void* src, bool pred) {
    int sz = pred ? 16 : 0;
    asm volatile("cp.async.cg.shared.global [%0], [%1], 16, %2;"
                 :: "r"(dst), "l"(src), "r"(sz) : "memory");
}
#define CP_COMMIT() asm volatile("cp.async.commit_group;" ::: "memory")
#define CP_WAIT2()  asm volatile("cp.async.wait_group 2;" ::: "memory")
#define CP_WAIT1()  asm volatile("cp.async.wait_group 1;" ::: "memory")
#define CP_WAIT0()  asm volatile("cp.async.wait_group 0;" ::: "memory")

#define MMA_TF32(acc, a, b)                                                   \
    asm volatile(                                                             \
        "mma.sync.aligned.m16n8k8.row.col.f32.tf32.tf32.f32 "                 \
        "{%0,%1,%2,%3}, {%4,%5,%6,%7}, {%8,%9}, {%0,%1,%2,%3};\n"             \
        : "+f"((acc)[0]), "+f"((acc)[1]), "+f"((acc)[2]), "+f"((acc)[3])      \
        : "r"((a)[0]), "r"((a)[1]), "r"((a)[2]), "r"((a)[3]),                 \
          "r"((b)[0]), "r"((b)[1]))

// ---------------------------------------------------------------------------
// Fused init: rounds 3 activations + 4 weights, builds rotary table.
// ---------------------------------------------------------------------------
__global__ __launch_bounds__(256) void init_k(
    const float* __restrict__ a0, const float* __restrict__ a1,
    const float* __restrict__ a2,
    const float* __restrict__ w0, const float* __restrict__ w1,
    const float* __restrict__ w2, const float* __restrict__ w3,
    float* __restrict__ da0, float* __restrict__ da1, float* __restrict__ da2,
    float* __restrict__ dw0, float* __restrict__ dw1,
    float* __restrict__ dw2, float* __restrict__ dw3,
    float2* __restrict__ T)
{
    int bid = blockIdx.x;
    if (bid < 9216) {
        int tz = bid / 3072;
        int idx = (bid % 3072) * 256 + threadIdx.x;
        const float* s = (tz == 0) ? a0 : (tz == 1) ? a1 : a2;
        float*       d = (tz == 0) ? da0 : (tz == 1) ? da1 : da2;
        float4 v = ((const float4*)s)[idx];
        v.x = round_tf32(v.x); v.y = round_tf32(v.y);
        v.z = round_tf32(v.z); v.w = round_tf32(v.w);
        ((float4*)d)[idx] = v;
    } else if (bid < 11520) {
        int r = bid - 9216;
        int tz = r / 576;
        int idx = (r % 576) * 256 + threadIdx.x;
        const float* s = (tz == 0) ? w0 : (tz == 1) ? w1 : (tz == 2) ? w2 : w3;
        float*       d = (tz == 0) ? dw0 : (tz == 1) ? dw1 : (tz == 2) ? dw2 : dw3;
        float4 v = ((const float4*)s)[idx];
        v.x = round_tf32(v.x); v.y = round_tf32(v.y);
        v.z = round_tf32(v.z); v.w = round_tf32(v.w);
        ((float4*)d)[idx] = v;
    } else {
        int tid = (bid - 11520) * 256 + threadIdx.x;
        int s = tid >> 5;
        int i = tid & 31;
        float inv_freq = expf(-(float)(2 * i) * (1.0f / 64.0f) * 9.210340371976184f);
        float ang = (float)s * inv_freq;
        float sn, cs;
        sincosf(ang, &sn, &cs);
        T[tid] = make_float2(sn, cs);
    }
}

// ---------------------------------------------------------------------------
// QKV GEMM (unchanged round-13 config): BM=128 BN=128 BK=32, 8 warps 2m x 4n,
// 3-stage cp.async, C head-major, round_z output rounding.
// ---------------------------------------------------------------------------
constexpr int AW = 36;
constexpr int BWp = 136;
constexpr int SAW = 128 * AW;
constexpr int SBW = 32 * BWp;
constexpr int STW = SAW + SBW;
constexpr int NST = 3;
constexpr int GEMM_SMEM = NST * STW * 4;
constexpr int ITERS = 24;

__global__ __launch_bounds__(256, 2) void tgemm_k(
    const float* __restrict__ A0, const float* __restrict__ A1, const float* __restrict__ A2,
    const float* __restrict__ Bm0, const float* __restrict__ Bm1, const float* __restrict__ Bm2,
    const float* __restrict__ bias0, const float* __restrict__ bias1, const float* __restrict__ bias2,
    float* __restrict__ C0, float* __restrict__ C1, float* __restrict__ C2,
    int M, int N, int K, int round_z)
{
    extern __shared__ float smf[];
    const uint32_t smb = (uint32_t)__cvta_generic_to_shared(smf);

    const int z = blockIdx.z;
    const float* A    = (z == 0) ? A0    : (z == 1) ? A1    : A2;
    const float* Bm   = (z == 0) ? Bm0   : (z == 1) ? Bm1   : Bm2;
    const float* bias = (z == 0) ? bias0 : (z == 1) ? bias1 : bias2;
    float*       C    = (z == 0) ? C0    : (z == 1) ? C1    : C2;

    const int t    = threadIdx.x;
    const int m0   = blockIdx.y * 128;
    const int n0   = blockIdx.x * 128;
    const int warp = t >> 5;
    const int lane = t & 31;
    const int wm   = (warp >> 2) * 64;
    const int wn   = (warp & 3) * 32;
    const int group = lane >> 2;
    const int tig   = lane & 3;

    const int ar = t >> 3;
    const int ac = (t & 7) * 4;
    const int br = t >> 3;
    const int bc = (t & 7) * 4;

    auto issue_stage = [&](int s, int k0) {
        const uint32_t abase = smb + (uint32_t)(s * STW) * 4;
        const uint32_t bbase = abase + SAW * 4;
#pragma unroll
        for (int i = 0; i < 4; i++) {
            int r = ar + i * 32;
            cpa16(abase + (uint32_t)(r * AW + ac) * 4,
                  &A[(size_t)(m0 + r) * K + k0 + ac]);
        }
#pragma unroll
        for (int j = 0; j < 4; j++) {
            int col = bc + j * 32;
            const float* src = Bm + (size_t)((n0 + col) >> 6) * K * 64
                                  + (size_t)(k0 + br) * 64 + (col & 63);
            cpa16(bbase + (uint32_t)(br * BWp + col) * 4, src);
        }
        CP_COMMIT();
    };

    float acc[4][4][4];
#pragma unroll
    for (int mt = 0; mt < 4; mt++)
#pragma unroll
        for (int nt = 0; nt < 4; nt++)
#pragma unroll
            for (int j = 0; j < 4; j++) acc[mt][nt][j] = 0.0f;

    issue_stage(0, 0);
    issue_stage(1, 32);

    for (int it = 0; it < ITERS; it++) {
        CP_WAIT1();
        __syncthreads();
        if (it + 2 < ITERS) issue_stage((it + 2) % NST, (it + 2) * 32);
        else                CP_COMMIT();

        const float* As = smf + (it % NST) * STW;
        const float* Bs = As + SAW;

#pragma unroll
        for (int kk = 0; kk < 4; kk++) {
            const int k8 = kk * 8;
            uint32_t a[4][4], b[4][2];
#pragma unroll
            for (int mt = 0; mt < 4; mt++) {
                int r = wm + mt * 16 + group;
                a[mt][0] = __float_as_uint(As[r * AW + k8 + tig]);
                a[mt][1] = __float_as_uint(As[(r + 8) * AW + k8 + tig]);
                a[mt][2] = __float_as_uint(As[r * AW + k8 + tig + 4]);
                a[mt][3] = __float_as_uint(As[(r + 8) * AW + k8 + tig + 4]);
            }
#pragma unroll
            for (int nt = 0; nt < 4; nt++) {
                int cc = wn + nt * 8 + group;
                b[nt][0] = __float_as_uint(Bs[(k8 + tig) * BWp + cc]);
                b[nt][1] = __float_as_uint(Bs[(k8 + tig + 4) * BWp + cc]);
            }
#pragma unroll
            for (int mt = 0; mt < 4; mt++)
#pragma unroll
                for (int nt = 0; nt < 4; nt++)
                    MMA_TF32(acc[mt][nt], a[mt], b[nt]);
        }
    }

    const bool rz = (z == round_z);
#pragma unroll
    for (int mt = 0; mt < 4; mt++) {
#pragma unroll
        for (int nt = 0; nt < 4; nt++) {
            int col  = n0 + wn + nt * 8 + tig * 2;
            float bx = bias[col];
            float by = bias[col + 1];
            int r0 = m0 + wm + mt * 16 + group;
            float2 o0 = make_float2(acc[mt][nt][0] + bx, acc[mt][nt][1] + by);
            float2 o1 = make_float2(acc[mt][nt][2] + bx, acc[mt][nt][3] + by);
            if (rz) {
                o0.x = round_tf32(o0.x); o0.y = round_tf32(o0.y);
                o1.x = round_tf32(o1.x); o1.y = round_tf32(o1.y);
            }
            int b2 = r0 >> 11, s2 = r0 & 2047;
            int h2 = col >> 6, d2 = col & 63;
            float* dst = &C[(((size_t)(b2 * Hh + h2)) << 17) + s2 * 64 + d2];
            *(float2*)dst         = o0;
            *(float2*)(dst + 512) = o1;
        }
    }
}

// ---------------------------------------------------------------------------
// WO GEMM: BM=128, BN=64, BK=32, 8 warps 4m x 2n (warp tile 32x32),
// *** 4-stage cp.async pipeline *** (prefetch distance 3 covers L2/DRAM
// latency; round-14 evidence: 2-stage exposed ~a full round trip per iter).
// 2 CTAs/SM (110.6 KB smem). A gathered from head-major Z, B row-major,
// C row-major + bias.
// ---------------------------------------------------------------------------
constexpr int BW64 = 72;                  // B pitch (72 % 32 = 8 -> conflict-free)
constexpr int SB64 = 32 * BW64;           // 2304
constexpr int STW64 = SAW + SB64;         // 6912
constexpr int NST64 = 4;
constexpr int GEMM64_SMEM = NST64 * STW64 * 4;   // 110592 B

__global__ __launch_bounds__(256, 2) void tgemm64_k(
    const float* __restrict__ A, const float* __restrict__ Bm,
    const float* __restrict__ bias, float* __restrict__ C,
    int M, int N, int K)
{
    extern __shared__ float smf[];
    const uint32_t smb = (uint32_t)__cvta_generic_to_shared(smf);

    const int t    = threadIdx.x;
    const int m0   = blockIdx.y * 128;
    const int n0   = blockIdx.x * 64;
    const int warp = t >> 5;
    const int lane = t & 31;
    const int wm   = (warp >> 1) * 32;   // 4 warps in m
    const int wn   = (warp & 1) * 32;    // 2 warps in n
    const int group = lane >> 2;
    const int tig   = lane & 3;

    const int ar = t >> 3;           // A rows ar + i*32
    const int ac = (t & 7) * 4;

    auto issue_stage = [&](int s, int k0) {
        const uint32_t abase = smb + (uint32_t)(s * STW64) * 4;
        const uint32_t bbase = abase + SAW * 4;
#pragma unroll
        for (int i = 0; i < 4; i++) {
            int r = ar + i * 32;
            int m  = m0 + r;
            int b2 = m >> 11, s2 = m & 2047;
            int k  = k0 + ac;
            int h2 = k >> 6,  d2 = k & 63;
            cpa16(abase + (uint32_t)(r * AW + ac) * 4,
                  &A[(((size_t)(b2 * Hh + h2)) << 17) + s2 * 64 + d2]);
        }
#pragma unroll
        for (int i = 0; i < 2; i++) {
            int idx = t + i * 256;
            int kr  = idx >> 4;
            int col = (idx & 15) * 4;
            cpa16(bbase + (uint32_t)(kr * BW64 + col) * 4,
                  Bm + (size_t)(k0 + kr) * N + n0 + col);
        }
        CP_COMMIT();
    };

    float acc[2][4][4];
#pragma unroll
    for (int mt = 0; mt < 2; mt++)
#pragma unroll
        for (int nt = 0; nt < 4; nt++)
#pragma unroll
            for (int j = 0; j < 4; j++) acc[mt][nt][j] = 0.0f;

    issue_stage(0, 0);
    issue_stage(1, 32);
    issue_stage(2, 64);

    for (int it = 0; it < ITERS; it++) {
        CP_WAIT2();            // 3 groups outstanding -> oldest (stage it) landed
        __syncthreads();       // also orders iter it-1 compute before stage reuse
        if (it + 3 < ITERS) issue_stage((it + 3) & 3, (it + 3) * 32);
        else                CP_COMMIT();   // empty group keeps wait accounting

        const float* As = smf + (it & 3) * STW64;
        const float* Bs = As + SAW;

#pragma unroll
        for (int kk = 0; kk < 4; kk++) {
            const int k8 = kk * 8;
            uint32_t a[2][4], b[4][2];
#pragma unroll
            for (int mt = 0; mt < 2; mt++) {
                int r = wm + mt * 16 + group;
                a[mt][0] = __float_as_uint(As[r * AW + k8 + tig]);
                a[mt][1] = __float_as_uint(As[(r + 8) * AW + k8 + tig]);
                a[mt][2] = __float_as_uint(As[r * AW + k8 + tig + 4]);
                a[mt][3] = __float_as_uint(As[(r + 8) * AW + k8 + tig + 4]);
            }
#pragma unroll
            for (int nt = 0; nt < 4; nt++) {
                int cc = wn + nt * 8 + group;
                b[nt][0] = __float_as_uint(Bs[(k8 + tig) * BW64 + cc]);
                b[nt][1] = __float_as_uint(Bs[(k8 + tig + 4) * BW64 + cc]);
            }
#pragma unroll
            for (int mt = 0; mt < 2; mt++)
#pragma unroll
                for (int nt = 0; nt < 4; nt++)
                    MMA_TF32(acc[mt][nt], a[mt], b[nt]);
        }
    }

#pragma unroll
    for (int mt = 0; mt < 2; mt++) {
#pragma unroll
        for (int nt = 0; nt < 4; nt++) {
            int col  = n0 + wn + nt * 8 + tig * 2;
            float bx = bias[col];
            float by = bias[col + 1];
            int r0 = m0 + wm + mt * 16 + group;
            float2 o0 = make_float2(acc[mt][nt][0] + bx, acc[mt][nt][1] + by);
            float2 o1 = make_float2(acc[mt][nt][2] + bx, acc[mt][nt][3] + by);
            *(float2*)&C[(size_t)r0 * N + col]       = o0;
            *(float2*)&C[(size_t)(r0 + 8) * N + col] = o1;
        }
    }
}

// ---------------------------------------------------------------------------
// Tensor-core sliding-window attention (unchanged round 13).
// ---------------------------------------------------------------------------
constexpr int QSP = 68;
constexpr int VPP = 72;
constexpr int KDP = 200;
constexpr int SCP = 196;
constexpr int OFF_KD = 4352;
constexpr int OFF_SC = 4608;
constexpr int OFF_V1 = 17152;
constexpr int ATTN_SMEM = (OFF_V1 + 64 * VPP) * 4;

__global__ __launch_bounds__(256) void attn_k(
    const float* __restrict__ Q, const float* __restrict__ K,
    const float* __restrict__ V, const float2* __restrict__ T,
    float* __restrict__ Z)
{
    extern __shared__ float sm[];
    const uint32_t smb = (uint32_t)__cvta_generic_to_shared(sm);
    float* Qs = sm;
    float* Kd = sm + OFF_KD;
    float* Sc = sm + OFF_SC;

    const int t  = threadIdx.x;
    const int q0 = blockIdx.x * 64;
    const int h  = blockIdx.y;
    const int b  = blockIdx.z;

    const int warp  = t >> 5;
    const int lane  = t & 31;
    const int group = lane >> 2;
    const int tig   = lane & 3;

    const size_t plane = ((size_t)(b * Hh + h)) << 17;
    const float* Qh = Q + plane;
    const float* Kh = K + plane;
    const float* Vh = V + plane;
    float*       Zh = Z + plane;

    auto issue_V = [&](int c, int vb) {
        const uint32_t vbase = smb + (uint32_t)(vb ? OFF_V1 : 0) * 4;
#pragma unroll
        for (int i = 0; i < 4; i++) {
            int idx = t + i * 256;
            int key = idx >> 4;
            int c4  = (idx & 15) * 4;
            int jg  = q0 - 128 + c * 64 + key;
            cpa16p(vbase + (uint32_t)(key * VPP + c4) * 4,
                   Vh + (size_t)jg * 64 + c4, jg >= 0);
        }
        CP_COMMIT();
    };

#pragma unroll
    for (int i = 0; i < 2; i++) {
        int idx = t + i * 256;
        int row = idx >> 3;
        int c4  = (idx & 7) * 4;
        int qg  = q0 + row;
        const float* src = Qh + (size_t)qg * 64;
        float4 x = *(const float4*)&src[c4];
        float4 y = *(const float4*)&src[c4 + 32];
        float xa[4] = {x.x, x.y, x.z, x.w};
        float ya[4] = {y.x, y.y, y.z, y.w};
        float4 lo, hi;
        float* lop = &lo.x; float* hip = &hi.x;
#pragma unroll
        for (int j = 0; j < 4; j++) {
            float2 sc = T[qg * 32 + c4 + j];
            lop[j] = round_tf32(xa[j] * sc.y - ya[j] * sc.x);
            hip[j] = round_tf32(ya[j] * sc.y + xa[j] * sc.x);
        }
        *(float4*)&Qs[row * QSP + c4]      = lo;
        *(float4*)&Qs[row * QSP + c4 + 32] = hi;
    }
#pragma unroll
    for (int i = 0; i < 6; i++) {
        int idx = t + i * 256;
        int key = idx >> 3;
        int c4  = (idx & 7) * 4;
        int jg  = q0 - 128 + key;
        float lov[4] = {0.f, 0.f, 0.f, 0.f};
        float hiv[4] = {0.f, 0.f, 0.f, 0.f};
        if (jg >= 0) {
            const float* src = Kh + (size_t)jg * 64;
            float4 x = *(const float4*)&src[c4];
            float4 y = *(const float4*)&src[c4 + 32];
            float xa[4] = {x.x, x.y, x.z, x.w};
            float ya[4] = {y.x, y.y, y.z, y.w};
#pragma unroll
            for (int j = 0; j < 4; j++) {
                float2 sc = T[jg * 32 + c4 + j];
                lov[j] = round_tf32(xa[j] * sc.y - ya[j] * sc.x);
                hiv[j] = round_tf32(ya[j] * sc.y + xa[j] * sc.x);
            }
        }
#pragma unroll
        for (int j = 0; j < 4; j++) {
            Kd[(c4 + j) * KDP + key]      = lov[j];
            Kd[(c4 + j + 32) * KDP + key] = hiv[j];
        }
    }
    __syncthreads();

    {
        const int wm = (warp >> 2) * 32;
        const int wn = (warp & 3) * 48;
        float acc[2][6][4];
#pragma unroll
        for (int mt = 0; mt < 2; mt++)
#pragma unroll
            for (int nt = 0; nt < 6; nt++)
#pragma unroll
                for (int j = 0; j < 4; j++) acc[mt][nt][j] = 0.0f;

#pragma unroll
        for (int kk = 0; kk < 8; kk++) {
            const int k8 = kk * 8;
            uint32_t a[2][4], bf[6][2];
#pragma unroll
            for (int mt = 0; mt < 2; mt++) {
                int r = wm + mt * 16 + group;
                a[mt][0] = __float_as_uint(Qs[r * QSP + k8 + tig]);
                a[mt][1] = __float_as_uint(Qs[(r + 8) * QSP + k8 + tig]);
                a[mt][2] = __float_as_uint(Qs[r * QSP + k8 + tig + 4]);
                a[mt][3] = __float_as_uint(Qs[(r + 8) * QSP + k8 + tig + 4]);
            }
#pragma unroll
            for (int nt = 0; nt < 6; nt++) {
                int col = wn + nt * 8 + group;
                bf[nt][0] = __float_as_uint(Kd[(k8 + tig) * KDP + col]);
                bf[nt][1] = __float_as_uint(Kd[(k8 + tig + 4) * KDP + col]);
            }
#pragma unroll
            for (int mt = 0; mt < 2; mt++)
#pragma unroll
                for (int nt = 0; nt < 6; nt++)
                    MMA_TF32(acc[mt][nt], a[mt], bf[nt]);
        }
        __syncthreads();

        issue_V(0, 0);
        issue_V(1, 1);

#pragma unroll
        for (int mt = 0; mt < 2; mt++) {
#pragma unroll
            for (int nt = 0; nt < 6; nt++) {
                int col = wn + nt * 8 + tig * 2;
                int jgl = q0 - 128 + col;
#pragma unroll
                for (int hl = 0; hl < 2; hl++) {
                    int r  = wm + mt * 16 + group + hl * 8;
                    int qg = q0 + r;
                    bool ok0 = (jgl >= 0) && (jgl <= qg) && (jgl > qg - WIN);
                    bool ok1 = (jgl + 1 >= 0) && (jgl + 1 <= qg) && (jgl + 1 > qg - WIN);
                    float2 o;
                    o.x = ok0 ? acc[mt][nt][hl * 2 + 0] * 0.125f : -1e30f;
                    o.y = ok1 ? acc[mt][nt][hl * 2 + 1] * 0.125f : -1e30f;
                    *(float2*)&Sc[r * SCP + col] = o;
                }
            }
        }
    }
    __syncthreads();

    {
        int r = t >> 2;
        int p = t & 3;
        float mx = -1e30f;
        for (int jj = p * 48; jj < p * 48 + 48; jj++)
            mx = fmaxf(mx, Sc[r * SCP + jj]);
        mx = fmaxf(mx, __shfl_xor_sync(0xFFFFFFFFu, mx, 1));
        mx = fmaxf(mx, __shfl_xor_sync(0xFFFFFFFFu, mx, 2));
        float sum = 0.0f;
        for (int jj = p * 48; jj < p * 48 + 48; jj++) {
            float e = __expf(Sc[r * SCP + jj] - mx);
            Sc[r * SCP + jj] = e;
            sum += e;
        }
        sum += __shfl_xor_sync(0xFFFFFFFFu, sum, 1);
        sum += __shfl_xor_sync(0xFFFFFFFFu, sum, 2);
        float inv = 1.0f / sum;
        for (int jj = p * 48; jj < p * 48 + 48; jj++)
            Sc[r * SCP + jj] = round_tf32(Sc[r * SCP + jj] * inv);
    }
    __syncthreads();

    {
        const int wm = (warp >> 2) * 32;
        const int wn = (warp & 3) * 16;
        float acc[2][2][4];
#pragma unroll
        for (int mt = 0; mt < 2; mt++)
#pragma unroll
            for (int nt = 0; nt < 2; nt++)
#pragma unroll
                for (int j = 0; j < 4; j++) acc[mt][nt][j] = 0.0f;

        for (int c = 0; c < 3; c++) {
            if (c < 2) { CP_WAIT1(); }
            else       { CP_WAIT0(); }
            __syncthreads();
            const float* Vv = sm + ((c & 1) ? OFF_V1 : 0);

#pragma unroll
            for (int kk = 0; kk < 8; kk++) {
                const int k8 = kk * 8;
                uint32_t a[2][4], bf[2][2];
#pragma unroll
                for (int mt = 0; mt < 2; mt++) {
                    int r = wm + mt * 16 + group;
                    int scol = c * 64 + k8 + tig;
                    a[mt][0] = __float_as_uint(Sc[r * SCP + scol]);
                    a[mt][1] = __float_as_uint(Sc[(r + 8) * SCP + scol]);
                    a[mt][2] = __float_as_uint(Sc[r * SCP + scol + 4]);
                    a[mt][3] = __float_as_uint(Sc[(r + 8) * SCP + scol + 4]);
                }
#pragma unroll
                for (int nt = 0; nt < 2; nt++) {
                    int dcol = wn + nt * 8 + group;
                    bf[nt][0] = __float_as_uint(Vv[(k8 + tig) * VPP + dcol]);
                    bf[nt][1] = __float_as_uint(Vv[(k8 + tig + 4) * VPP + dcol]);
                }
#pragma unroll
                for (int mt = 0; mt < 2; mt++)
#pragma unroll
                    for (int nt = 0; nt < 2; nt++)
                        MMA_TF32(acc[mt][nt], a[mt], bf[nt]);
            }

            if (c == 0) {
                __syncthreads();
                issue_V(2, 0);
            }
        }

#pragma unroll
        for (int mt = 0; mt < 2; mt++) {
#pragma unroll
            for (int nt = 0; nt < 2; nt++) {
                int col = wn + nt * 8 + tig * 2;
#pragma unroll
                for (int hl = 0; hl < 2; hl++) {
                    int r = wm + mt * 16 + group + hl * 8;
                    float2 o;
                    o.x = round_tf32(acc[mt][nt][hl * 2 + 0]);
                    o.y = round_tf32(acc[mt][nt][hl * 2 + 1]);
                    *(float2*)&Zh[(size_t)(q0 + r) * 64 + col] = o;
                }
            }
        }
    }
}

// ---------------------------------------------------------------------------
extern "C" void kernel_launch(void* const* d_in, const int* in_sizes, int n_in,
                              void* d_out, int out_size)
{
    const float* qin = (const float*)d_in[0];
    const float* kin = (const float*)d_in[1];
    const float* vin = (const float*)d_in[2];
    const float* WQ  = (const float*)d_in[3];
    const float* WK  = (const float*)d_in[4];
    const float* WV  = (const float*)d_in[5];
    const float* WO  = (const float*)d_in[6];
    const float* bQ  = (const float*)d_in[7];
    const float* bK  = (const float*)d_in[8];
    const float* bV  = (const float*)d_in[9];
    const float* bO  = (const float*)d_in[10];
    float* out = (float*)d_out;

    float *pQ, *pK, *pV, *pZ;
    float *pAq, *pAk, *pAv, *pWq, *pWk, *pWv, *pWo;
    float2* pT;
    cudaGetSymbolAddress((void**)&pQ, g_Q);
    cudaGetSymbolAddress((void**)&pK, g_K);
    cudaGetSymbolAddress((void**)&pV, g_V);
    cudaGetSymbolAddress((void**)&pZ, g_Z);
    cudaGetSymbolAddress((void**)&pAq, g_Aq);
    cudaGetSymbolAddress((void**)&pAk, g_Ak);
    cudaGetSymbolAddress((void**)&pAv, g_Av);
    cudaGetSymbolAddress((void**)&pWq, g_Wq);
    cudaGetSymbolAddress((void**)&pWk, g_Wk);
    cudaGetSymbolAddress((void**)&pWv, g_Wv);
    cudaGetSymbolAddress((void**)&pWo, g_Wo);
    cudaGetSymbolAddress((void**)&pT, g_T);

    const int M = Bb * Ss;       // 4096
    const int N = Hh * DHd;      // 768
    const int Kd = Dd;           // 768

    cudaFuncSetAttribute(tgemm_k,
                         cudaFuncAttributeMaxDynamicSharedMemorySize, GEMM_SMEM);
    cudaFuncSetAttribute(tgemm64_k,
                         cudaFuncAttributeMaxDynamicSharedMemorySize, GEMM64_SMEM);
    cudaFuncSetAttribute(attn_k,
                         cudaFuncAttributeMaxDynamicSharedMemorySize, ATTN_SMEM);

    // Fused init: pre-round operands + rotary table
    init_k<<<11776, 256>>>(qin, kin, vin, WQ, WK, WV, WO,
                           pAq, pAk, pAv, pWq, pWk, pWv, pWo, pT);

    // Fused QKV projections (C head-major; V output pre-rounded: round_z=2)
    tgemm_k<<<dim3(N / 128, M / 128, 3), 256, GEMM_SMEM>>>(
        pAq, pAk, pAv, pWq, pWk, pWv, bQ, bK, bV, pQ, pK, pV, M, N, Kd, 2);

    // Attention (head-major; rotary fused; V double-buffered cp.async)
    attn_k<<<dim3(Ss / 64, Hh, Bb), 256, ATTN_SMEM>>>(pQ, pK, pV, pT, pZ);

    // Output projection: BN=64, 4-stage pipeline
    tgemm64_k<<<dim3(N / 64, M / 128), 256, GEMM64_SMEM>>>(
        pZ, pWo, bO, out, M, N, Kd);
}

// round 16
// speedup vs baseline: 1.3859x; 1.3859x over previous
#include <cuda_runtime.h>
#include <cuda_fp16.h>
#include <math.h>
#include <stdint.h>

// Problem constants
constexpr int Bb = 2;
constexpr int Ss = 2048;
constexpr int Dd = 768;
constexpr int Hh = 12;
constexpr int DHd = 64;
constexpr int WIN = 128;

// Scratch (device globals; no allocation allowed)
// Q/K/Z HEAD-MAJOR fp16: [b][h][s][d], plane stride 1<<17. V fp32 head-major.
__device__ __align__(16) __half g_Qh[Bb * Hh * Ss * DHd];
__device__ __align__(16) __half g_Kh[Bb * Hh * Ss * DHd];
__device__ __align__(16) float  g_V [Bb * Hh * Ss * DHd];
__device__ __align__(16) __half g_Zh[Bb * Hh * Ss * DHd];
// fp16 activations (row-major [m][k]) and transposed fp16 weights [n][k]
__device__ __align__(16) __half g_Aq[Bb * Ss * Dd];
__device__ __align__(16) __half g_Ak[Bb * Ss * Dd];
__device__ __align__(16) __half g_Av[Bb * Ss * Dd];
__device__ __align__(16) __half g_Wqn[Dd * Dd];
__device__ __align__(16) __half g_Wkn[Dd * Dd];
__device__ __align__(16) __half g_Wvn[Dd * Dd];
__device__ __align__(16) __half g_Won[Dd * Dd];
// rotary sin/cos table: [pos][freq] -> (sin, cos)
__device__ __align__(16) float2 g_T[Ss * 32];

__device__ __forceinline__ uint32_t f2tf32(float x) {
    uint32_t u;
    asm("cvt.rna.tf32.f32 %0, %1;" : "=r"(u) : "f"(x));
    return u;
}
__device__ __forceinline__ float round_tf32(float x) {
    return __uint_as_float(f2tf32(x));
}
__device__ __forceinline__ void cpa16(uint32_t dst, const void* src) {
    asm volatile("cp.async.cg.shared.global [%0], [%1], 16;"
                 :: "r"(dst), "l"(src) : "memory");
}
__device__ __forceinline__ void cpa16p(uint32_t dst, const void* src, bool pred) {
    int sz = pred ? 16 : 0;
    asm volatile("cp.async.cg.shared.global [%0], [%1], 16, %2;"
                 :: "r"(dst), "l"(src), "r"(sz) : "memory");
}
#define CP_COMMIT() asm volatile("cp.async.commit_group;" ::: "memory")
#define CP_WAIT1()  asm volatile("cp.async.wait_group 1;" ::: "memory")
#define CP_WAIT0()  asm volatile("cp.async.wait_group 0;" ::: "memory")

#define MMA_F16(acc, a, b)                                                    \
    asm volatile(                                                             \
        "mma.sync.aligned.m16n8k16.row.col.f32.f16.f16.f32 "                  \
        "{%0,%1,%2,%3}, {%4,%5,%6,%7}, {%8,%9}, {%0,%1,%2,%3};\n"             \
        : "+f"((acc)[0]), "+f"((acc)[1]), "+f"((acc)[2]), "+f"((acc)[3])      \
        : "r"((a)[0]), "r"((a)[1]), "r"((a)[2]), "r"((a)[3]),                 \
          "r"((b)[0]), "r"((b)[1]))

#define MMA_TF32(acc, a, b)                                                   \
    asm volatile(                                                             \
        "mma.sync.aligned.m16n8k8.row.col.f32.tf32.tf32.f32 "                 \
        "{%0,%1,%2,%3}, {%4,%5,%6,%7}, {%8,%9}, {%0,%1,%2,%3};\n"             \
        : "+f"((acc)[0]), "+f"((acc)[1]), "+f"((acc)[2]), "+f"((acc)[3])      \
        : "r"((a)[0]), "r"((a)[1]), "r"((a)[2]), "r"((a)[3]),                 \
          "r"((b)[0]), "r"((b)[1]))

// ---------------------------------------------------------------------------
// Fused init:
//  [0,9216)      activations -> fp16
//  [9216,11520)  weight transpose+convert: Wq/Wk/Wv [h][768k][64n] and
//                Wo [768k][768n] -> [n][k] fp16 (32x32 smem tiles)
//  [11520,11776) rotary table
// ---------------------------------------------------------------------------
__global__ __launch_bounds__(256) void init_k(
    const float* __restrict__ a0, const float* __restrict__ a1,
    const float* __restrict__ a2,
    const float* __restrict__ w0, const float* __restrict__ w1,
    const float* __restrict__ w2, const float* __restrict__ w3,
    __half* __restrict__ da0, __half* __restrict__ da1, __half* __restrict__ da2,
    __half* __restrict__ dw0, __half* __restrict__ dw1,
    __half* __restrict__ dw2, __half* __restrict__ dw3,
    float2* __restrict__ T)
{
    __shared__ float sm[32][33];
    int bid = blockIdx.x;
    int t = threadIdx.x;
    if (bid < 9216) {
        int tz = bid / 3072;
        int idx = (bid % 3072) * 256 + t;
        const float* s = (tz == 0) ? a0 : (tz == 1) ? a1 : a2;
        __half*      d = (tz == 0) ? da0 : (tz == 1) ? da1 : da2;
        float4 v = ((const float4*)s)[idx];
        __half2 h0 = __floats2half2_rn(v.x, v.y);
        __half2 h1 = __floats2half2_rn(v.z, v.w);
        uint2 u;
        u.x = *(uint32_t*)&h0;
        u.y = *(uint32_t*)&h1;
        ((uint2*)d)[idx] = u;
    } else if (bid < 11520) {
        int wi = bid - 9216;
        int tz = wi / 576;
        int ti = wi % 576;
        const float* W = (tz == 0) ? w0 : (tz == 1) ? w1 : (tz == 2) ? w2 : w3;
        __half*      O = (tz == 0) ? dw0 : (tz == 1) ? dw1 : (tz == 2) ? dw2 : dw3;
        int k0, nbase, ldn;
        const float* inb;
        if (tz < 3) {
            int h  = ti / 48;
            int tt = ti % 48;
            k0    = (tt >> 1) * 32;
            nbase = h * 64 + (tt & 1) * 32;
            ldn   = 64;
            inb   = W + (size_t)h * 768 * 64;
        } else {
            k0    = (ti / 24) * 32;
            nbase = (ti % 24) * 32;
            ldn   = 768;
            inb   = W;
        }
        int nlo = (tz < 3) ? ((ti % 48) & 1) * 32 : nbase;
#pragma unroll
        for (int p = 0; p < 4; p++) {
            int kr = p * 8 + (t >> 5);
            int nc = t & 31;
            sm[kr][nc] = inb[(size_t)(k0 + kr) * ldn + nlo + nc];
        }
        __syncthreads();
#pragma unroll
        for (int p = 0; p < 4; p++) {
            int nr = p * 8 + (t >> 5);
            int kc = t & 31;
            O[(size_t)(nbase + nr) * 768 + k0 + kc] = __float2half_rn(sm[kc][nr]);
        }
    } else {
        int tid = (bid - 11520) * 256 + t;
        int s = tid >> 5;
        int i = tid & 31;
        float inv_freq = expf(-(float)(2 * i) * (1.0f / 64.0f) * 9.210340371976184f);
        float ang = (float)s * inv_freq;
        float sn, cs;
        sincosf(ang, &sn, &cs);
        T[tid] = make_float2(sn, cs);
    }
}

// ---------------------------------------------------------------------------
// QKV fp16 GEMM: BM=128 BN=128 BK=32, 8 warps 2m x 4n (warp 64x32),
// 3-stage cp.async. A fp16 [m][k]; B fp16 [n][k] (transposed weights).
// C: z<2 -> fp16 head-major; z==2 -> fp32 tf32-rounded head-major (V).
// Smem pitches 40 halves -> conflict-free fragment LDS (bank (4g+t)%32 etc).
// ---------------------------------------------------------------------------
constexpr int HP = 40;                       // pitch in halves
constexpr int SAH = 128 * HP;                // 5120 halves
constexpr int SBH = 128 * HP;                // 5120
constexpr int STH = SAH + SBH;               // 10240 halves = 20480 B
constexpr int GEMM_SMEM = 3 * STH * 2;       // 61440 B
constexpr int ITERS = 24;

__global__ __launch_bounds__(256, 2) void hgemm_k(
    const __half* __restrict__ A0, const __half* __restrict__ A1, const __half* __restrict__ A2,
    const __half* __restrict__ Bn0, const __half* __restrict__ Bn1, const __half* __restrict__ Bn2,
    const float* __restrict__ bias0, const float* __restrict__ bias1, const float* __restrict__ bias2,
    __half* __restrict__ C0, __half* __restrict__ C1, float* __restrict__ C2,
    int M, int N, int K)
{
    extern __shared__ __half smh[];
    const uint32_t smb = (uint32_t)__cvta_generic_to_shared(smh);

    const int z = blockIdx.z;
    const __half* A    = (z == 0) ? A0 : (z == 1) ? A1 : A2;
    const __half* Bn   = (z == 0) ? Bn0 : (z == 1) ? Bn1 : Bn2;
    const float*  bias = (z == 0) ? bias0 : (z == 1) ? bias1 : bias2;

    const int t    = threadIdx.x;
    const int m0   = blockIdx.y * 128;
    const int n0   = blockIdx.x * 128;
    const int warp = t >> 5;
    const int lane = t & 31;
    const int wm   = (warp >> 2) * 64;
    const int wn   = (warp & 3) * 32;
    const int group = lane >> 2;
    const int tig   = lane & 3;

    const int lr = t >> 2;          // loader row 0..63 (x2 passes -> 128)
    const int lc = (t & 3) * 8;     // halves 0,8,16,24

    auto issue_stage = [&](int s, int k0) {
        const uint32_t abase = smb + (uint32_t)(s * STH) * 2;
        const uint32_t bbase = abase + SAH * 2;
#pragma unroll
        for (int i = 0; i < 2; i++) {
            int r = lr + i * 64;
            cpa16(abase + (uint32_t)(r * HP + lc) * 2,
                  &A[(size_t)(m0 + r) * K + k0 + lc]);
        }
#pragma unroll
        for (int i = 0; i < 2; i++) {
            int n = lr + i * 64;
            cpa16(bbase + (uint32_t)(n * HP + lc) * 2,
                  &Bn[(size_t)(n0 + n) * K + k0 + lc]);
        }
        CP_COMMIT();
    };

    float acc[4][4][4];
#pragma unroll
    for (int mt = 0; mt < 4; mt++)
#pragma unroll
        for (int nt = 0; nt < 4; nt++)
#pragma unroll
            for (int j = 0; j < 4; j++) acc[mt][nt][j] = 0.0f;

    issue_stage(0, 0);
    issue_stage(1, 32);

    for (int it = 0; it < ITERS; it++) {
        CP_WAIT1();
        __syncthreads();
        if (it + 2 < ITERS) issue_stage((it + 2) % 3, (it + 2) * 32);
        else                CP_COMMIT();

        const __half* As = smh + (it % 3) * STH;
        const __half* Bs = As + SAH;

#pragma unroll
        for (int kk = 0; kk < 2; kk++) {
            const int ka = kk * 16 + tig * 2;
            uint32_t a[4][4], b[4][2];
#pragma unroll
            for (int mt = 0; mt < 4; mt++) {
                int r = wm + mt * 16 + group;
                a[mt][0] = *(const uint32_t*)&As[r * HP + ka];
                a[mt][1] = *(const uint32_t*)&As[(r + 8) * HP + ka];
                a[mt][2] = *(const uint32_t*)&As[r * HP + ka + 8];
                a[mt][3] = *(const uint32_t*)&As[(r + 8) * HP + ka + 8];
            }
#pragma unroll
            for (int nt = 0; nt < 4; nt++) {
                int n = wn + nt * 8 + group;
                b[nt][0] = *(const uint32_t*)&Bs[n * HP + ka];
                b[nt][1] = *(const uint32_t*)&Bs[n * HP + ka + 8];
            }
#pragma unroll
            for (int mt = 0; mt < 4; mt++)
#pragma unroll
                for (int nt = 0; nt < 4; nt++)
                    MMA_F16(acc[mt][nt], a[mt], b[nt]);
        }
    }

#pragma unroll
    for (int mt = 0; mt < 4; mt++) {
#pragma unroll
        for (int nt = 0; nt < 4; nt++) {
            int col  = n0 + wn + nt * 8 + tig * 2;
            float bx = bias[col];
            float by = bias[col + 1];
            int r0 = m0 + wm + mt * 16 + group;
            int b2 = r0 >> 11, s2 = r0 & 2047;
            int h2 = col >> 6, d2 = col & 63;
            size_t off = (((size_t)(b2 * Hh + h2)) << 17) + s2 * 64 + d2;
            float o00 = acc[mt][nt][0] + bx, o01 = acc[mt][nt][1] + by;
            float o10 = acc[mt][nt][2] + bx, o11 = acc[mt][nt][3] + by;
            if (z == 2) {
                float2 f0 = make_float2(round_tf32(o00), round_tf32(o01));
                float2 f1 = make_float2(round_tf32(o10), round_tf32(o11));
                *(float2*)&C2[off]       = f0;
                *(float2*)&C2[off + 512] = f1;
            } else {
                __half* Ch = (z == 0) ? C0 : C1;
                __half2 h0 = __floats2half2_rn(o00, o01);
                __half2 h1 = __floats2half2_rn(o10, o11);
                *(__half2*)&Ch[off]       = h0;
                *(__half2*)&Ch[off + 512] = h1;
            }
        }
    }
}

// ---------------------------------------------------------------------------
// WO fp16 GEMM: BM=128 BN=64 BK=32, 8 warps 4m x 2n (warp 32x32), 3-stage,
// 3 CTAs/SM. A = Zh fp16 head-major gather; B = Won [n][k]; C fp32 + bias.
// ---------------------------------------------------------------------------
constexpr int SB64H = 64 * HP;                  // 2560 halves
constexpr int ST64H = SAH + SB64H;              // 7680 halves = 15360 B
constexpr int GEMM64_SMEM = 3 * ST64H * 2;      // 46080 B

__global__ __launch_bounds__(256, 3) void hgemm64_k(
    const __half* __restrict__ A, const __half* __restrict__ Bn,
    const float* __restrict__ bias, float* __restrict__ C,
    int M, int N, int K)
{
    extern __shared__ __half smh[];
    const uint32_t smb = (uint32_t)__cvta_generic_to_shared(smh);

    const int t    = threadIdx.x;
    const int m0   = blockIdx.y * 128;
    const int n0   = blockIdx.x * 64;
    const int warp = t >> 5;
    const int lane = t & 31;
    const int wm   = (warp >> 1) * 32;   // 4 warps in m
    const int wn   = (warp & 1) * 32;    // 2 warps in n
    const int group = lane >> 2;
    const int tig   = lane & 3;

    const int lr = t >> 2;
    const int lc = (t & 3) * 8;

    auto issue_stage = [&](int s, int k0) {
        const uint32_t abase = smb + (uint32_t)(s * ST64H) * 2;
        const uint32_t bbase = abase + SAH * 2;
#pragma unroll
        for (int i = 0; i < 2; i++) {
            int r = lr + i * 64;
            int m  = m0 + r;
            int b2 = m >> 11, s2 = m & 2047;
            int k  = k0 + lc;
            int h2 = k >> 6, d2 = k & 63;
            cpa16(abase + (uint32_t)(r * HP + lc) * 2,
                  &A[(((size_t)(b2 * Hh + h2)) << 17) + s2 * 64 + d2]);
        }
        {
            int n = lr;   // 0..63
            cpa16(bbase + (uint32_t)(n * HP + lc) * 2,
                  &Bn[(size_t)(n0 + n) * K + k0 + lc]);
        }
        CP_COMMIT();
    };

    float acc[2][4][4];
#pragma unroll
    for (int mt = 0; mt < 2; mt++)
#pragma unroll
        for (int nt = 0; nt < 4; nt++)
#pragma unroll
            for (int j = 0; j < 4; j++) acc[mt][nt][j] = 0.0f;

    issue_stage(0, 0);
    issue_stage(1, 32);

    for (int it = 0; it < ITERS; it++) {
        CP_WAIT1();
        __syncthreads();
        if (it + 2 < ITERS) issue_stage((it + 2) % 3, (it + 2) * 32);
        else                CP_COMMIT();

        const __half* As = smh + (it % 3) * ST64H;
        const __half* Bs = As + SAH;

#pragma unroll
        for (int kk = 0; kk < 2; kk++) {
            const int ka = kk * 16 + tig * 2;
            uint32_t a[2][4], b[4][2];
#pragma unroll
            for (int mt = 0; mt < 2; mt++) {
                int r = wm + mt * 16 + group;
                a[mt][0] = *(const uint32_t*)&As[r * HP + ka];
                a[mt][1] = *(const uint32_t*)&As[(r + 8) * HP + ka];
                a[mt][2] = *(const uint32_t*)&As[r * HP + ka + 8];
                a[mt][3] = *(const uint32_t*)&As[(r + 8) * HP + ka + 8];
            }
#pragma unroll
            for (int nt = 0; nt < 4; nt++) {
                int n = wn + nt * 8 + group;
                b[nt][0] = *(const uint32_t*)&Bs[n * HP + ka];
                b[nt][1] = *(const uint32_t*)&Bs[n * HP + ka + 8];
            }
#pragma unroll
            for (int mt = 0; mt < 2; mt++)
#pragma unroll
                for (int nt = 0; nt < 4; nt++)
                    MMA_F16(acc[mt][nt], a[mt], b[nt]);
        }
    }

#pragma unroll
    for (int mt = 0; mt < 2; mt++) {
#pragma unroll
        for (int nt = 0; nt < 4; nt++) {
            int col  = n0 + wn + nt * 8 + tig * 2;
            float bx = bias[col];
            float by = bias[col + 1];
            int r0 = m0 + wm + mt * 16 + group;
            float2 o0 = make_float2(acc[mt][nt][0] + bx, acc[mt][nt][1] + by);
            float2 o1 = make_float2(acc[mt][nt][2] + bx, acc[mt][nt][3] + by);
            *(float2*)&C[(size_t)r0 * N + col]       = o0;
            *(float2*)&C[(size_t)(r0 + 8) * N + col] = o1;
        }
    }
}

// ---------------------------------------------------------------------------
// Attention: scores via fp16 mma (Q/K fp16, rotary fused at load), softmax
// fp32, PV via tf32 mma (V fp32 double-buffered cp.async), Z written fp16.
// Smem bytes: Qs(h)@0 [64][72] 9216 | Kd(h)@9216 [192][72] 27648 |
//             Sc(f)@36864 [64][196] 50176 | V0(f)@0 / V1(f)@18432 [64][72]
// ---------------------------------------------------------------------------
constexpr int AQP = 72;    // Qs/Kd pitch (halves); bank (4g+t)%32 conflict-free
constexpr int VPP = 72;    // V pitch (floats)
constexpr int SCP = 196;   // Sc pitch (floats)
constexpr int OFFB_KD = 9216;
constexpr int OFFB_SC = 36864;
constexpr int OFFB_V1 = 18432;
constexpr int ATTN_SMEM = OFFB_SC + 64 * SCP * 4;   // 87040 B

__global__ __launch_bounds__(256) void attn_k(
    const __half* __restrict__ Q, const __half* __restrict__ K,
    const float* __restrict__ V, const float2* __restrict__ T,
    __half* __restrict__ Z)
{
    extern __shared__ char smc[];
    const uint32_t smb = (uint32_t)__cvta_generic_to_shared(smc);
    __half* Qs = (__half*)smc;
    __half* Kd = (__half*)(smc + OFFB_KD);
    float*  Sc = (float*)(smc + OFFB_SC);

    const int t  = threadIdx.x;
    const int q0 = blockIdx.x * 64;
    const int h  = blockIdx.y;
    const int b  = blockIdx.z;

    const int warp  = t >> 5;
    const int lane  = t & 31;
    const int group = lane >> 2;
    const int tig   = lane & 3;

    const size_t plane = ((size_t)(b * Hh + h)) << 17;
    const __half* Qh = Q + plane;
    const __half* Kh = K + plane;
    const float*  Vh = V + plane;
    __half*       Zh = Z + plane;

    auto issue_V = [&](int c, int vb) {
        const uint32_t vbase = smb + (vb ? OFFB_V1 : 0);
#pragma unroll
        for (int i = 0; i < 4; i++) {
            int idx = t + i * 256;
            int key = idx >> 4;
            int c4  = (idx & 15) * 4;
            int jg  = q0 - 128 + c * 64 + key;
            cpa16p(vbase + (uint32_t)(key * VPP + c4) * 4,
                   Vh + (size_t)jg * 64 + c4, jg >= 0);
        }
        CP_COMMIT();
    };

    // rotate 8 (d, d+32) pairs given packed inputs; returns packed fp16
    auto rot8 = [&](uint4 ulo, uint4 uhi, int pos, int dbase, uint4& olo, uint4& ohi) {
        __half2* pl = (__half2*)&ulo;
        __half2* ph = (__half2*)&uhi;
        __half2* ql = (__half2*)&olo;
        __half2* qh = (__half2*)&ohi;
#pragma unroll
        for (int jj = 0; jj < 4; jj++) {
            float2 x2 = __half22float2(pl[jj]);
            float2 y2 = __half22float2(ph[jj]);
            float2 s0 = T[pos * 32 + dbase + jj * 2];
            float2 s1 = T[pos * 32 + dbase + jj * 2 + 1];
            ql[jj] = __floats2half2_rn(x2.x * s0.y - y2.x * s0.x,
                                       x2.y * s1.y - y2.y * s1.x);
            qh[jj] = __floats2half2_rn(y2.x * s0.y + x2.x * s0.x,
                                       y2.y * s1.y + x2.y * s1.x);
        }
    };

    // ---- Q loader: 64 rows x 4 quarters, rotate, fp16 [q][d] ----
    {
        int row = t >> 2;
        int q8  = (t & 3) * 8;
        int qg  = q0 + row;
        uint4 ulo = *(const uint4*)&Qh[(size_t)qg * 64 + q8];
        uint4 uhi = *(const uint4*)&Qh[(size_t)qg * 64 + q8 + 32];
        uint4 olo, ohi;
        rot8(ulo, uhi, qg, q8, olo, ohi);
        *(uint4*)&Qs[row * AQP + q8]      = olo;
        *(uint4*)&Qs[row * AQP + q8 + 32] = ohi;
    }
    // ---- K loader: 192 keys x 4 quarters, rotate, fp16 [key][d] ----
#pragma unroll
    for (int i = 0; i < 3; i++) {
        int idx = t + i * 256;
        int key = idx >> 2;
        int q8  = (idx & 3) * 8;
        int jg  = q0 - 128 + key;
        uint4 olo = make_uint4(0, 0, 0, 0), ohi = make_uint4(0, 0, 0, 0);
        if (jg >= 0) {
            uint4 ulo = *(const uint4*)&Kh[(size_t)jg * 64 + q8];
            uint4 uhi = *(const uint4*)&Kh[(size_t)jg * 64 + q8 + 32];
            rot8(ulo, uhi, jg, q8, olo, ohi);
        }
        *(uint4*)&Kd[key * AQP + q8]      = olo;
        *(uint4*)&Kd[key * AQP + q8 + 32] = ohi;
    }
    __syncthreads();

    // ---- scores fp16 mma: warp tile 32q x 48key, K=64 in 4 k16 steps ----
    {
        const int wm = (warp >> 2) * 32;
        const int wn = (warp & 3) * 48;
        float acc[2][6][4];
#pragma unroll
        for (int mt = 0; mt < 2; mt++)
#pragma unroll
            for (int nt = 0; nt < 6; nt++)
#pragma unroll
                for (int j = 0; j < 4; j++) acc[mt][nt][j] = 0.0f;

#pragma unroll
        for (int kk = 0; kk < 4; kk++) {
            const int ka = kk * 16 + tig * 2;
            uint32_t a[2][4], bf[6][2];
#pragma unroll
            for (int mt = 0; mt < 2; mt++) {
                int r = wm + mt * 16 + group;
                a[mt][0] = *(const uint32_t*)&Qs[r * AQP + ka];
                a[mt][1] = *(const uint32_t*)&Qs[(r + 8) * AQP + ka];
                a[mt][2] = *(const uint32_t*)&Qs[r * AQP + ka + 8];
                a[mt][3] = *(const uint32_t*)&Qs[(r + 8) * AQP + ka + 8];
            }
#pragma unroll
            for (int nt = 0; nt < 6; nt++) {
                int n = wn + nt * 8 + group;
                bf[nt][0] = *(const uint32_t*)&Kd[n * AQP + ka];
                bf[nt][1] = *(const uint32_t*)&Kd[n * AQP + ka + 8];
            }
#pragma unroll
            for (int mt = 0; mt < 2; mt++)
#pragma unroll
                for (int nt = 0; nt < 6; nt++)
                    MMA_F16(acc[mt][nt], a[mt], bf[nt]);
        }
        __syncthreads();   // Qs/Kd reads done; V streaming may overwrite

        issue_V(0, 0);
        issue_V(1, 1);

        // masked/scaled epilogue -> Sc (fp32)
#pragma unroll
        for (int mt = 0; mt < 2; mt++) {
#pragma unroll
            for (int nt = 0; nt < 6; nt++) {
                int col = wn + nt * 8 + tig * 2;
                int jgl = q0 - 128 + col;
#pragma unroll
                for (int hl = 0; hl < 2; hl++) {
                    int r  = wm + mt * 16 + group + hl * 8;
                    int qg = q0 + r;
                    bool ok0 = (jgl >= 0) && (jgl <= qg) && (jgl > qg - WIN);
                    bool ok1 = (jgl + 1 >= 0) && (jgl + 1 <= qg) && (jgl + 1 > qg - WIN);
                    float2 o;
                    o.x = ok0 ? acc[mt][nt][hl * 2 + 0] * 0.125f : -1e30f;
                    o.y = ok1 ? acc[mt][nt][hl * 2 + 1] * 0.125f : -1e30f;
                    *(float2*)&Sc[r * SCP + col] = o;
                }
            }
        }
    }
    __syncthreads();

    // ---- softmax (fp32), P tf32-rounded for PV ----
    {
        int r = t >> 2;
        int p = t & 3;
        float mx = -1e30f;
        for (int jj = p * 48; jj < p * 48 + 48; jj++)
            mx = fmaxf(mx, Sc[r * SCP + jj]);
        mx = fmaxf(mx, __shfl_xor_sync(0xFFFFFFFFu, mx, 1));
        mx = fmaxf(mx, __shfl_xor_sync(0xFFFFFFFFu, mx, 2));
        float sum = 0.0f;
        for (int jj = p * 48; jj < p * 48 + 48; jj++) {
            float e = __expf(Sc[r * SCP + jj] - mx);
            Sc[r * SCP + jj] = e;
            sum += e;
        }
        sum += __shfl_xor_sync(0xFFFFFFFFu, sum, 1);
        sum += __shfl_xor_sync(0xFFFFFFFFu, sum, 2);
        float inv = 1.0f / sum;
        for (int jj = p * 48; jj < p * 48 + 48; jj++)
            Sc[r * SCP + jj] = round_tf32(Sc[r * SCP + jj] * inv);
    }
    __syncthreads();

    // ---- PV tf32 mma: warp tile 32q x 16d, 3 double-buffered V chunks ----
    {
        const int wm = (warp >> 2) * 32;
        const int wn = (warp & 3) * 16;
        float acc[2][2][4];
#pragma unroll
        for (int mt = 0; mt < 2; mt++)
#pragma unroll
            for (int nt = 0; nt < 2; nt++)
#pragma unroll
                for (int j = 0; j < 4; j++) acc[mt][nt][j] = 0.0f;

        for (int c = 0; c < 3; c++) {
            if (c < 2) { CP_WAIT1(); }
            else       { CP_WAIT0(); }
            __syncthreads();
            const float* Vv = (const float*)(smc + ((c & 1) ? OFFB_V1 : 0));

#pragma unroll
            for (int kk = 0; kk < 8; kk++) {
                const int k8 = kk * 8;
                uint32_t a[2][4], bf[2][2];
#pragma unroll
                for (int mt = 0; mt < 2; mt++) {
                    int r = wm + mt * 16 + group;
                    int scol = c * 64 + k8 + tig;
                    a[mt][0] = __float_as_uint(Sc[r * SCP + scol]);
                    a[mt][1] = __float_as_uint(Sc[(r + 8) * SCP + scol]);
                    a[mt][2] = __float_as_uint(Sc[r * SCP + scol + 4]);
                    a[mt][3] = __float_as_uint(Sc[(r + 8) * SCP + scol + 4]);
                }
#pragma unroll
                for (int nt = 0; nt < 2; nt++) {
                    int dcol = wn + nt * 8 + group;
                    bf[nt][0] = __float_as_uint(Vv[(k8 + tig) * VPP + dcol]);
                    bf[nt][1] = __float_as_uint(Vv[(k8 + tig + 4) * VPP + dcol]);
                }
#pragma unroll
                for (int mt = 0; mt < 2; mt++)
#pragma unroll
                    for (int nt = 0; nt < 2; nt++)
                        MMA_TF32(acc[mt][nt], a[mt], bf[nt]);
            }

            if (c == 0) {
                __syncthreads();
                issue_V(2, 0);
            }
        }

        // epilogue -> Z fp16 head-major
#pragma unroll
        for (int mt = 0; mt < 2; mt++) {
#pragma unroll
            for (int nt = 0; nt < 2; nt++) {
                int col = wn + nt * 8 + tig * 2;
#pragma unroll
                for (int hl = 0; hl < 2; hl++) {
                    int r = wm + mt * 16 + group + hl * 8;
                    __half2 o = __floats2half2_rn(acc[mt][nt][hl * 2 + 0],
                                                  acc[mt][nt][hl * 2 + 1]);
                    *(__half2*)&Zh[(size_t)(q0 + r) * 64 + col] = o;
                }
            }
        }
    }
}

// ---------------------------------------------------------------------------
extern "C" void kernel_launch(void* const* d_in, const int* in_sizes, int n_in,
                              void* d_out, int out_size)
{
    const float* qin = (const float*)d_in[0];
    const float* kin = (const float*)d_in[1];
    const float* vin = (const float*)d_in[2];
    const float* WQ  = (const float*)d_in[3];
    const float* WK  = (const float*)d_in[4];
    const float* WV  = (const float*)d_in[5];
    const float* WO  = (const float*)d_in[6];
    const float* bQ  = (const float*)d_in[7];
    const float* bK  = (const float*)d_in[8];
    const float* bV  = (const float*)d_in[9];
    const float* bO  = (const float*)d_in[10];
    float* out = (float*)d_out;

    __half *pQ, *pK, *pZ, *pAq, *pAk, *pAv, *pWq, *pWk, *pWv, *pWo;
    float *pV;
    float2* pT;
    cudaGetSymbolAddress((void**)&pQ, g_Qh);
    cudaGetSymbolAddress((void**)&pK, g_Kh);
    cudaGetSymbolAddress((void**)&pV, g_V);
    cudaGetSymbolAddress((void**)&pZ, g_Zh);
    cudaGetSymbolAddress((void**)&pAq, g_Aq);
    cudaGetSymbolAddress((void**)&pAk, g_Ak);
    cudaGetSymbolAddress((void**)&pAv, g_Av);
    cudaGetSymbolAddress((void**)&pWq, g_Wqn);
    cudaGetSymbolAddress((void**)&pWk, g_Wkn);
    cudaGetSymbolAddress((void**)&pWv, g_Wvn);
    cudaGetSymbolAddress((void**)&pWo, g_Won);
    cudaGetSymbolAddress((void**)&pT, g_T);

    const int M = Bb * Ss;       // 4096
    const int N = Hh * DHd;      // 768
    const int Kd = Dd;           // 768

    cudaFuncSetAttribute(hgemm_k,
                         cudaFuncAttributeMaxDynamicSharedMemorySize, GEMM_SMEM);
    cudaFuncSetAttribute(hgemm64_k,
                         cudaFuncAttributeMaxDynamicSharedMemorySize, GEMM64_SMEM);
    cudaFuncSetAttribute(attn_k,
                         cudaFuncAttributeMaxDynamicSharedMemorySize, ATTN_SMEM);

    // Fused init: fp16 conversion + weight transposes + rotary table
    init_k<<<11776, 256>>>(qin, kin, vin, WQ, WK, WV, WO,
                           pAq, pAk, pAv, pWq, pWk, pWv, pWo, pT);

    // Fused QKV projections (Q/K fp16, V fp32 tf32-rounded; head-major)
    hgemm_k<<<dim3(N / 128, M / 128, 3), 256, GEMM_SMEM>>>(
        pAq, pAk, pAv, pWq, pWk, pWv, bQ, bK, bV, pQ, pK, pV, M, N, Kd);

    // Attention (scores fp16 mma, PV tf32; Z fp16)
    attn_k<<<dim3(Ss / 64, Hh, Bb), 256, ATTN_SMEM>>>(pQ, pK, pV, pT, pZ);

    // Output projection (fp16 mma, fp32 out)
    hgemm64_k<<<dim3(N / 64, M / 128), 256, GEMM64_SMEM>>>(
        pZ, pWo, bO, out, M, N, Kd);
}

// round 17
// speedup vs baseline: 1.4893x; 1.0746x over previous
#include <cuda_runtime.h>
#include <cuda_fp16.h>
#include <math.h>
#include <stdint.h>

// Problem constants
constexpr int Bb = 2;
constexpr int Ss = 2048;
constexpr int Dd = 768;
constexpr int Hh = 12;
constexpr int DHd = 64;
constexpr int WIN = 128;

// Scratch (device globals; no allocation allowed)
// Q/K/Z HEAD-MAJOR fp16: [b][h][s][d], plane stride 1<<17. V fp32 head-major.
__device__ __align__(16) __half g_Qh[Bb * Hh * Ss * DHd];
__device__ __align__(16) __half g_Kh[Bb * Hh * Ss * DHd];
__device__ __align__(16) float  g_V [Bb * Hh * Ss * DHd];
__device__ __align__(16) __half g_Zh[Bb * Hh * Ss * DHd];
// fp16 activations (row-major [m][k]) and transposed fp16 weights [n][k]
__device__ __align__(16) __half g_Aq[Bb * Ss * Dd];
__device__ __align__(16) __half g_Ak[Bb * Ss * Dd];
__device__ __align__(16) __half g_Av[Bb * Ss * Dd];
__device__ __align__(16) __half g_Wqn[Dd * Dd];
__device__ __align__(16) __half g_Wkn[Dd * Dd];
__device__ __align__(16) __half g_Wvn[Dd * Dd];
__device__ __align__(16) __half g_Won[Dd * Dd];
// rotary sin/cos table: [pos][freq] -> (sin, cos)
__device__ __align__(16) float2 g_T[Ss * 32];

__device__ __forceinline__ uint32_t f2tf32(float x) {
    uint32_t u;
    asm("cvt.rna.tf32.f32 %0, %1;" : "=r"(u) : "f"(x));
    return u;
}
__device__ __forceinline__ float round_tf32(float x) {
    return __uint_as_float(f2tf32(x));
}
__device__ __forceinline__ void cpa16(uint32_t dst, const void* src) {
    asm volatile("cp.async.cg.shared.global [%0], [%1], 16;"
                 :: "r"(dst), "l"(src) : "memory");
}
__device__ __forceinline__ void cpa16p(uint32_t dst, const void* src, bool pred) {
    int sz = pred ? 16 : 0;
    asm volatile("cp.async.cg.shared.global [%0], [%1], 16, %2;"
                 :: "r"(dst), "l"(src), "r"(sz) : "memory");
}
#define CP_COMMIT() asm volatile("cp.async.commit_group;" ::: "memory")
#define CP_WAIT1()  asm volatile("cp.async.wait_group 1;" ::: "memory")
#define CP_WAIT0()  asm volatile("cp.async.wait_group 0;" ::: "memory")

#define MMA_F16(acc, a, b)                                                    \
    asm volatile(                                                             \
        "mma.sync.aligned.m16n8k16.row.col.f32.f16.f16.f32 "                  \
        "{%0,%1,%2,%3}, {%4,%5,%6,%7}, {%8,%9}, {%0,%1,%2,%3};\n"             \
        : "+f"((acc)[0]), "+f"((acc)[1]), "+f"((acc)[2]), "+f"((acc)[3])      \
        : "r"((a)[0]), "r"((a)[1]), "r"((a)[2]), "r"((a)[3]),                 \
          "r"((b)[0]), "r"((b)[1]))

#define MMA_TF32(acc, a, b)                                                   \
    asm volatile(                                                             \
        "mma.sync.aligned.m16n8k8.row.col.f32.tf32.tf32.f32 "                 \
        "{%0,%1,%2,%3}, {%4,%5,%6,%7}, {%8,%9}, {%0,%1,%2,%3};\n"             \
        : "+f"((acc)[0]), "+f"((acc)[1]), "+f"((acc)[2]), "+f"((acc)[3])      \
        : "r"((a)[0]), "r"((a)[1]), "r"((a)[2]), "r"((a)[3]),                 \
          "r"((b)[0]), "r"((b)[1]))

// ---------------------------------------------------------------------------
// Fused init (unchanged round 16): activations->fp16, weights transpose+cvt,
// rotary table.
// ---------------------------------------------------------------------------
__global__ __launch_bounds__(256) void init_k(
    const float* __restrict__ a0, const float* __restrict__ a1,
    const float* __restrict__ a2,
    const float* __restrict__ w0, const float* __restrict__ w1,
    const float* __restrict__ w2, const float* __restrict__ w3,
    __half* __restrict__ da0, __half* __restrict__ da1, __half* __restrict__ da2,
    __half* __restrict__ dw0, __half* __restrict__ dw1,
    __half* __restrict__ dw2, __half* __restrict__ dw3,
    float2* __restrict__ T)
{
    __shared__ float sm[32][33];
    int bid = blockIdx.x;
    int t = threadIdx.x;
    if (bid < 9216) {
        int tz = bid / 3072;
        int idx = (bid % 3072) * 256 + t;
        const float* s = (tz == 0) ? a0 : (tz == 1) ? a1 : a2;
        __half*      d = (tz == 0) ? da0 : (tz == 1) ? da1 : da2;
        float4 v = ((const float4*)s)[idx];
        __half2 h0 = __floats2half2_rn(v.x, v.y);
        __half2 h1 = __floats2half2_rn(v.z, v.w);
        uint2 u;
        u.x = *(uint32_t*)&h0;
        u.y = *(uint32_t*)&h1;
        ((uint2*)d)[idx] = u;
    } else if (bid < 11520) {
        int wi = bid - 9216;
        int tz = wi / 576;
        int ti = wi % 576;
        const float* W = (tz == 0) ? w0 : (tz == 1) ? w1 : (tz == 2) ? w2 : w3;
        __half*      O = (tz == 0) ? dw0 : (tz == 1) ? dw1 : (tz == 2) ? dw2 : dw3;
        int k0, nbase, ldn;
        const float* inb;
        if (tz < 3) {
            int h  = ti / 48;
            int tt = ti % 48;
            k0    = (tt >> 1) * 32;
            nbase = h * 64 + (tt & 1) * 32;
            ldn   = 64;
            inb   = W + (size_t)h * 768 * 64;
        } else {
            k0    = (ti / 24) * 32;
            nbase = (ti % 24) * 32;
            ldn   = 768;
            inb   = W;
        }
        int nlo = (tz < 3) ? ((ti % 48) & 1) * 32 : nbase;
#pragma unroll
        for (int p = 0; p < 4; p++) {
            int kr = p * 8 + (t >> 5);
            int nc = t & 31;
            sm[kr][nc] = inb[(size_t)(k0 + kr) * ldn + nlo + nc];
        }
        __syncthreads();
#pragma unroll
        for (int p = 0; p < 4; p++) {
            int nr = p * 8 + (t >> 5);
            int kc = t & 31;
            O[(size_t)(nbase + nr) * 768 + k0 + kc] = __float2half_rn(sm[kc][nr]);
        }
    } else {
        int tid = (bid - 11520) * 256 + t;
        int s = tid >> 5;
        int i = tid & 31;
        float inv_freq = expf(-(float)(2 * i) * (1.0f / 64.0f) * 9.210340371976184f);
        float ang = (float)s * inv_freq;
        float sn, cs;
        sincosf(ang, &sn, &cs);
        T[tid] = make_float2(sn, cs);
    }
}

// ---------------------------------------------------------------------------
// QKV fp16 GEMM: BM=128 BN=128 *** BK=64 (ITERS=12) ***, 8 warps 2m x 4n,
// 3-stage cp.async. Pitch 72 halves -> conflict-free frags ((4r+tig)%32).
// ---------------------------------------------------------------------------
constexpr int HPK = 72;                      // pitch in halves (BK=64 + 8)
constexpr int SAH = 128 * HPK;               // 9216 halves
constexpr int STH = 2 * SAH;                 // A+B, 18432 halves = 36864 B
constexpr int GEMM_SMEM = 3 * STH * 2;       // 110592 B
constexpr int ITERS = 12;                    // 768 / 64

__global__ __launch_bounds__(256, 2) void hgemm_k(
    const __half* __restrict__ A0, const __half* __restrict__ A1, const __half* __restrict__ A2,
    const __half* __restrict__ Bn0, const __half* __restrict__ Bn1, const __half* __restrict__ Bn2,
    const float* __restrict__ bias0, const float* __restrict__ bias1, const float* __restrict__ bias2,
    __half* __restrict__ C0, __half* __restrict__ C1, float* __restrict__ C2,
    int M, int N, int K)
{
    extern __shared__ __half smh[];
    const uint32_t smb = (uint32_t)__cvta_generic_to_shared(smh);

    const int z = blockIdx.z;
    const __half* A    = (z == 0) ? A0 : (z == 1) ? A1 : A2;
    const __half* Bn   = (z == 0) ? Bn0 : (z == 1) ? Bn1 : Bn2;
    const float*  bias = (z == 0) ? bias0 : (z == 1) ? bias1 : bias2;

    const int t    = threadIdx.x;
    const int m0   = blockIdx.y * 128;
    const int n0   = blockIdx.x * 128;
    const int warp = t >> 5;
    const int lane = t & 31;
    const int wm   = (warp >> 2) * 64;
    const int wn   = (warp & 3) * 32;
    const int group = lane >> 2;
    const int tig   = lane & 3;

    const int lr = t >> 3;          // 0..31
    const int lc = (t & 7) * 8;     // 0..56 halves

    auto issue_stage = [&](int s, int k0) {
        const uint32_t abase = smb + (uint32_t)(s * STH) * 2;
        const uint32_t bbase = abase + SAH * 2;
#pragma unroll
        for (int i = 0; i < 4; i++) {
            int r = lr + i * 32;
            cpa16(abase + (uint32_t)(r * HPK + lc) * 2,
                  &A[(size_t)(m0 + r) * K + k0 + lc]);
        }
#pragma unroll
        for (int i = 0; i < 4; i++) {
            int n = lr + i * 32;
            cpa16(bbase + (uint32_t)(n * HPK + lc) * 2,
                  &Bn[(size_t)(n0 + n) * K + k0 + lc]);
        }
        CP_COMMIT();
    };

    float acc[4][4][4];
#pragma unroll
    for (int mt = 0; mt < 4; mt++)
#pragma unroll
        for (int nt = 0; nt < 4; nt++)
#pragma unroll
            for (int j = 0; j < 4; j++) acc[mt][nt][j] = 0.0f;

    issue_stage(0, 0);
    issue_stage(1, 64);

    for (int it = 0; it < ITERS; it++) {
        CP_WAIT1();
        __syncthreads();
        if (it + 2 < ITERS) issue_stage((it + 2) % 3, (it + 2) * 64);
        else                CP_COMMIT();

        const __half* As = smh + (it % 3) * STH;
        const __half* Bs = As + SAH;

#pragma unroll
        for (int kk = 0; kk < 4; kk++) {
            const int ka = kk * 16 + tig * 2;
            uint32_t a[4][4], b[4][2];
#pragma unroll
            for (int mt = 0; mt < 4; mt++) {
                int r = wm + mt * 16 + group;
                a[mt][0] = *(const uint32_t*)&As[r * HPK + ka];
                a[mt][1] = *(const uint32_t*)&As[(r + 8) * HPK + ka];
                a[mt][2] = *(const uint32_t*)&As[r * HPK + ka + 8];
                a[mt][3] = *(const uint32_t*)&As[(r + 8) * HPK + ka + 8];
            }
#pragma unroll
            for (int nt = 0; nt < 4; nt++) {
                int n = wn + nt * 8 + group;
                b[nt][0] = *(const uint32_t*)&Bs[n * HPK + ka];
                b[nt][1] = *(const uint32_t*)&Bs[n * HPK + ka + 8];
            }
#pragma unroll
            for (int mt = 0; mt < 4; mt++)
#pragma unroll
                for (int nt = 0; nt < 4; nt++)
                    MMA_F16(acc[mt][nt], a[mt], b[nt]);
        }
    }

#pragma unroll
    for (int mt = 0; mt < 4; mt++) {
#pragma unroll
        for (int nt = 0; nt < 4; nt++) {
            int col  = n0 + wn + nt * 8 + tig * 2;
            float bx = bias[col];
            float by = bias[col + 1];
            int r0 = m0 + wm + mt * 16 + group;
            int b2 = r0 >> 11, s2 = r0 & 2047;
            int h2 = col >> 6, d2 = col & 63;
            size_t off = (((size_t)(b2 * Hh + h2)) << 17) + s2 * 64 + d2;
            float o00 = acc[mt][nt][0] + bx, o01 = acc[mt][nt][1] + by;
            float o10 = acc[mt][nt][2] + bx, o11 = acc[mt][nt][3] + by;
            if (z == 2) {
                float2 f0 = make_float2(round_tf32(o00), round_tf32(o01));
                float2 f1 = make_float2(round_tf32(o10), round_tf32(o11));
                *(float2*)&C2[off]       = f0;
                *(float2*)&C2[off + 512] = f1;
            } else {
                __half* Ch = (z == 0) ? C0 : C1;
                __half2 h0 = __floats2half2_rn(o00, o01);
                __half2 h1 = __floats2half2_rn(o10, o11);
                *(__half2*)&Ch[off]       = h0;
                *(__half2*)&Ch[off + 512] = h1;
            }
        }
    }
}

// ---------------------------------------------------------------------------
// WO fp16 GEMM: BM=128 BN=64 *** BK=64 (ITERS=12) ***, 8 warps 4m x 2n,
// 3-stage cp.async, 2 CTAs/SM.
// ---------------------------------------------------------------------------
constexpr int SB64H = 64 * HPK;                 // 4608 halves
constexpr int ST64H = SAH + SB64H;              // 13824 halves = 27648 B
constexpr int GEMM64_SMEM = 3 * ST64H * 2;      // 82944 B

__global__ __launch_bounds__(256, 2) void hgemm64_k(
    const __half* __restrict__ A, const __half* __restrict__ Bn,
    const float* __restrict__ bias, float* __restrict__ C,
    int M, int N, int K)
{
    extern __shared__ __half smh[];
    const uint32_t smb = (uint32_t)__cvta_generic_to_shared(smh);

    const int t    = threadIdx.x;
    const int m0   = blockIdx.y * 128;
    const int n0   = blockIdx.x * 64;
    const int warp = t >> 5;
    const int lane = t & 31;
    const int wm   = (warp >> 1) * 32;   // 4 warps in m
    const int wn   = (warp & 1) * 32;    // 2 warps in n
    const int group = lane >> 2;
    const int tig   = lane & 3;

    const int lr = t >> 3;          // 0..31
    const int lc = (t & 7) * 8;

    auto issue_stage = [&](int s, int k0) {
        const uint32_t abase = smb + (uint32_t)(s * ST64H) * 2;
        const uint32_t bbase = abase + SAH * 2;
#pragma unroll
        for (int i = 0; i < 4; i++) {
            int r = lr + i * 32;
            int m  = m0 + r;
            int b2 = m >> 11, s2 = m & 2047;
            int k  = k0 + lc;
            int h2 = k >> 6, d2 = k & 63;
            cpa16(abase + (uint32_t)(r * HPK + lc) * 2,
                  &A[(((size_t)(b2 * Hh + h2)) << 17) + s2 * 64 + d2]);
        }
#pragma unroll
        for (int i = 0; i < 2; i++) {
            int n = lr + i * 32;     // 0..63
            cpa16(bbase + (uint32_t)(n * HPK + lc) * 2,
                  &Bn[(size_t)(n0 + n) * K + k0 + lc]);
        }
        CP_COMMIT();
    };

    float acc[2][4][4];
#pragma unroll
    for (int mt = 0; mt < 2; mt++)
#pragma unroll
        for (int nt = 0; nt < 4; nt++)
#pragma unroll
            for (int j = 0; j < 4; j++) acc[mt][nt][j] = 0.0f;

    issue_stage(0, 0);
    issue_stage(1, 64);

    for (int it = 0; it < ITERS; it++) {
        CP_WAIT1();
        __syncthreads();
        if (it + 2 < ITERS) issue_stage((it + 2) % 3, (it + 2) * 64);
        else                CP_COMMIT();

        const __half* As = smh + (it % 3) * ST64H;
        const __half* Bs = As + SAH;

#pragma unroll
        for (int kk = 0; kk < 4; kk++) {
            const int ka = kk * 16 + tig * 2;
            uint32_t a[2][4], b[4][2];
#pragma unroll
            for (int mt = 0; mt < 2; mt++) {
                int r = wm + mt * 16 + group;
                a[mt][0] = *(const uint32_t*)&As[r * HPK + ka];
                a[mt][1] = *(const uint32_t*)&As[(r + 8) * HPK + ka];
                a[mt][2] = *(const uint32_t*)&As[r * HPK + ka + 8];
                a[mt][3] = *(const uint32_t*)&As[(r + 8) * HPK + ka + 8];
            }
#pragma unroll
            for (int nt = 0; nt < 4; nt++) {
                int n = wn + nt * 8 + group;
                b[nt][0] = *(const uint32_t*)&Bs[n * HPK + ka];
                b[nt][1] = *(const uint32_t*)&Bs[n * HPK + ka + 8];
            }
#pragma unroll
            for (int mt = 0; mt < 2; mt++)
#pragma unroll
                for (int nt = 0; nt < 4; nt++)
                    MMA_F16(acc[mt][nt], a[mt], b[nt]);
        }
    }

#pragma unroll
    for (int mt = 0; mt < 2; mt++) {
#pragma unroll
        for (int nt = 0; nt < 4; nt++) {
            int col  = n0 + wn + nt * 8 + tig * 2;
            float bx = bias[col];
            float by = bias[col + 1];
            int r0 = m0 + wm + mt * 16 + group;
            float2 o0 = make_float2(acc[mt][nt][0] + bx, acc[mt][nt][1] + by);
            float2 o1 = make_float2(acc[mt][nt][2] + bx, acc[mt][nt][3] + by);
            *(float2*)&C[(size_t)r0 * N + col]       = o0;
            *(float2*)&C[(size_t)(r0 + 8) * N + col] = o1;
        }
    }
}

// ---------------------------------------------------------------------------
// Attention (unchanged round 16): scores fp16 mma, softmax fp32, PV tf32.
// ---------------------------------------------------------------------------
constexpr int AQP = 72;
constexpr int VPP = 72;
constexpr int SCP = 196;
constexpr int OFFB_KD = 9216;
constexpr int OFFB_SC = 36864;
constexpr int OFFB_V1 = 18432;
constexpr int ATTN_SMEM = OFFB_SC + 64 * SCP * 4;

__global__ __launch_bounds__(256) void attn_k(
    const __half* __restrict__ Q, const __half* __restrict__ K,
    const float* __restrict__ V, const float2* __restrict__ T,
    __half* __restrict__ Z)
{
    extern __shared__ char smc[];
    const uint32_t smb = (uint32_t)__cvta_generic_to_shared(smc);
    __half* Qs = (__half*)smc;
    __half* Kd = (__half*)(smc + OFFB_KD);
    float*  Sc = (float*)(smc + OFFB_SC);

    const int t  = threadIdx.x;
    const int q0 = blockIdx.x * 64;
    const int h  = blockIdx.y;
    const int b  = blockIdx.z;

    const int warp  = t >> 5;
    const int lane  = t & 31;
    const int group = lane >> 2;
    const int tig   = lane & 3;

    const size_t plane = ((size_t)(b * Hh + h)) << 17;
    const __half* Qh = Q + plane;
    const __half* Kh = K + plane;
    const float*  Vh = V + plane;
    __half*       Zh = Z + plane;

    auto issue_V = [&](int c, int vb) {
        const uint32_t vbase = smb + (vb ? OFFB_V1 : 0);
#pragma unroll
        for (int i = 0; i < 4; i++) {
            int idx = t + i * 256;
            int key = idx >> 4;
            int c4  = (idx & 15) * 4;
            int jg  = q0 - 128 + c * 64 + key;
            cpa16p(vbase + (uint32_t)(key * VPP + c4) * 4,
                   Vh + (size_t)jg * 64 + c4, jg >= 0);
        }
        CP_COMMIT();
    };

    auto rot8 = [&](uint4 ulo, uint4 uhi, int pos, int dbase, uint4& olo, uint4& ohi) {
        __half2* pl = (__half2*)&ulo;
        __half2* ph = (__half2*)&uhi;
        __half2* ql = (__half2*)&olo;
        __half2* qh = (__half2*)&ohi;
#pragma unroll
        for (int jj = 0; jj < 4; jj++) {
            float2 x2 = __half22float2(pl[jj]);
            float2 y2 = __half22float2(ph[jj]);
            float2 s0 = T[pos * 32 + dbase + jj * 2];
            float2 s1 = T[pos * 32 + dbase + jj * 2 + 1];
            ql[jj] = __floats2half2_rn(x2.x * s0.y - y2.x * s0.x,
                                       x2.y * s1.y - y2.y * s1.x);
            qh[jj] = __floats2half2_rn(y2.x * s0.y + x2.x * s0.x,
                                       y2.y * s1.y + x2.y * s1.x);
        }
    };

    {
        int row = t >> 2;
        int q8  = (t & 3) * 8;
        int qg  = q0 + row;
        uint4 ulo = *(const uint4*)&Qh[(size_t)qg * 64 + q8];
        uint4 uhi = *(const uint4*)&Qh[(size_t)qg * 64 + q8 + 32];
        uint4 olo, ohi;
        rot8(ulo, uhi, qg, q8, olo, ohi);
        *(uint4*)&Qs[row * AQP + q8]      = olo;
        *(uint4*)&Qs[row * AQP + q8 + 32] = ohi;
    }
#pragma unroll
    for (int i = 0; i < 3; i++) {
        int idx = t + i * 256;
        int key = idx >> 2;
        int q8  = (idx & 3) * 8;
        int jg  = q0 - 128 + key;
        uint4 olo = make_uint4(0, 0, 0, 0), ohi = make_uint4(0, 0, 0, 0);
        if (jg >= 0) {
            uint4 ulo = *(const uint4*)&Kh[(size_t)jg * 64 + q8];
            uint4 uhi = *(const uint4*)&Kh[(size_t)jg * 64 + q8 + 32];
            rot8(ulo, uhi, jg, q8, olo, ohi);
        }
        *(uint4*)&Kd[key * AQP + q8]      = olo;
        *(uint4*)&Kd[key * AQP + q8 + 32] = ohi;
    }
    __syncthreads();

    {
        const int wm = (warp >> 2) * 32;
        const int wn = (warp & 3) * 48;
        float acc[2][6][4];
#pragma unroll
        for (int mt = 0; mt < 2; mt++)
#pragma unroll
            for (int nt = 0; nt < 6; nt++)
#pragma unroll
                for (int j = 0; j < 4; j++) acc[mt][nt][j] = 0.0f;

#pragma unroll
        for (int kk = 0; kk < 4; kk++) {
            const int ka = kk * 16 + tig * 2;
            uint32_t a[2][4], bf[6][2];
#pragma unroll
            for (int mt = 0; mt < 2; mt++) {
                int r = wm + mt * 16 + group;
                a[mt][0] = *(const uint32_t*)&Qs[r * AQP + ka];
                a[mt][1] = *(const uint32_t*)&Qs[(r + 8) * AQP + ka];
                a[mt][2] = *(const uint32_t*)&Qs[r * AQP + ka + 8];
                a[mt][3] = *(const uint32_t*)&Qs[(r + 8) * AQP + ka + 8];
            }
#pragma unroll
            for (int nt = 0; nt < 6; nt++) {
                int n = wn + nt * 8 + group;
                bf[nt][0] = *(const uint32_t*)&Kd[n * AQP + ka];
                bf[nt][1] = *(const uint32_t*)&Kd[n * AQP + ka + 8];
            }
#pragma unroll
            for (int mt = 0; mt < 2; mt++)
#pragma unroll
                for (int nt = 0; nt < 6; nt++)
                    MMA_F16(acc[mt][nt], a[mt], bf[nt]);
        }
        __syncthreads();

        issue_V(0, 0);
        issue_V(1, 1);

#pragma unroll
        for (int mt = 0; mt < 2; mt++) {
#pragma unroll
            for (int nt = 0; nt < 6; nt++) {
                int col = wn + nt * 8 + tig * 2;
                int jgl = q0 - 128 + col;
#pragma unroll
                for (int hl = 0; hl < 2; hl++) {
                    int r  = wm + mt * 16 + group + hl * 8;
                    int qg = q0 + r;
                    bool ok0 = (jgl >= 0) && (jgl <= qg) && (jgl > qg - WIN);
                    bool ok1 = (jgl + 1 >= 0) && (jgl + 1 <= qg) && (jgl + 1 > qg - WIN);
                    float2 o;
                    o.x = ok0 ? acc[mt][nt][hl * 2 + 0] * 0.125f : -1e30f;
                    o.y = ok1 ? acc[mt][nt][hl * 2 + 1] * 0.125f : -1e30f;
                    *(float2*)&Sc[r * SCP + col] = o;
                }
            }
        }
    }
    __syncthreads();

    {
        int r = t >> 2;
        int p = t & 3;
        float mx = -1e30f;
        for (int jj = p * 48; jj < p * 48 + 48; jj++)
            mx = fmaxf(mx, Sc[r * SCP + jj]);
        mx = fmaxf(mx, __shfl_xor_sync(0xFFFFFFFFu, mx, 1));
        mx = fmaxf(mx, __shfl_xor_sync(0xFFFFFFFFu, mx, 2));
        float sum = 0.0f;
        for (int jj = p * 48; jj < p * 48 + 48; jj++) {
            float e = __expf(Sc[r * SCP + jj] - mx);
            Sc[r * SCP + jj] = e;
            sum += e;
        }
        sum += __shfl_xor_sync(0xFFFFFFFFu, sum, 1);
        sum += __shfl_xor_sync(0xFFFFFFFFu, sum, 2);
        float inv = 1.0f / sum;
        for (int jj = p * 48; jj < p * 48 + 48; jj++)
            Sc[r * SCP + jj] = round_tf32(Sc[r * SCP + jj] * inv);
    }
    __syncthreads();

    {
        const int wm = (warp >> 2) * 32;
        const int wn = (warp & 3) * 16;
        float acc[2][2][4];
#pragma unroll
        for (int mt = 0; mt < 2; mt++)
#pragma unroll
            for (int nt = 0; nt < 2; nt++)
#pragma unroll
                for (int j = 0; j < 4; j++) acc[mt][nt][j] = 0.0f;

        for (int c = 0; c < 3; c++) {
            if (c < 2) { CP_WAIT1(); }
            else       { CP_WAIT0(); }
            __syncthreads();
            const float* Vv = (const float*)(smc + ((c & 1) ? OFFB_V1 : 0));

#pragma unroll
            for (int kk = 0; kk < 8; kk++) {
                const int k8 = kk * 8;
                uint32_t a[2][4], bf[2][2];
#pragma unroll
                for (int mt = 0; mt < 2; mt++) {
                    int r = wm + mt * 16 + group;
                    int scol = c * 64 + k8 + tig;
                    a[mt][0] = __float_as_uint(Sc[r * SCP + scol]);
                    a[mt][1] = __float_as_uint(Sc[(r + 8) * SCP + scol]);
                    a[mt][2] = __float_as_uint(Sc[r * SCP + scol + 4]);
                    a[mt][3] = __float_as_uint(Sc[(r + 8) * SCP + scol + 4]);
                }
#pragma unroll
                for (int nt = 0; nt < 2; nt++) {
                    int dcol = wn + nt * 8 + group;
                    bf[nt][0] = __float_as_uint(Vv[(k8 + tig) * VPP + dcol]);
                    bf[nt][1] = __float_as_uint(Vv[(k8 + tig + 4) * VPP + dcol]);
                }
#pragma unroll
                for (int mt = 0; mt < 2; mt++)
#pragma unroll
                    for (int nt = 0; nt < 2; nt++)
                        MMA_TF32(acc[mt][nt], a[mt], bf[nt]);
            }

            if (c == 0) {
                __syncthreads();
                issue_V(2, 0);
            }
        }

#pragma unroll
        for (int mt = 0; mt < 2; mt++) {
#pragma unroll
            for (int nt = 0; nt < 2; nt++) {
                int col = wn + nt * 8 + tig * 2;
#pragma unroll
                for (int hl = 0; hl < 2; hl++) {
                    int r = wm + mt * 16 + group + hl * 8;
                    __half2 o = __floats2half2_rn(acc[mt][nt][hl * 2 + 0],
                                                  acc[mt][nt][hl * 2 + 1]);
                    *(__half2*)&Zh[(size_t)(q0 + r) * 64 + col] = o;
                }
            }
        }
    }
}

// ---------------------------------------------------------------------------
extern "C" void kernel_launch(void* const* d_in, const int* in_sizes, int n_in,
                              void* d_out, int out_size)
{
    const float* qin = (const float*)d_in[0];
    const float* kin = (const float*)d_in[1];
    const float* vin = (const float*)d_in[2];
    const float* WQ  = (const float*)d_in[3];
    const float* WK  = (const float*)d_in[4];
    const float* WV  = (const float*)d_in[5];
    const float* WO  = (const float*)d_in[6];
    const float* bQ  = (const float*)d_in[7];
    const float* bK  = (const float*)d_in[8];
    const float* bV  = (const float*)d_in[9];
    const float* bO  = (const float*)d_in[10];
    float* out = (float*)d_out;

    __half *pQ, *pK, *pZ, *pAq, *pAk, *pAv, *pWq, *pWk, *pWv, *pWo;
    float *pV;
    float2* pT;
    cudaGetSymbolAddress((void**)&pQ, g_Qh);
    cudaGetSymbolAddress((void**)&pK, g_Kh);
    cudaGetSymbolAddress((void**)&pV, g_V);
    cudaGetSymbolAddress((void**)&pZ, g_Zh);
    cudaGetSymbolAddress((void**)&pAq, g_Aq);
    cudaGetSymbolAddress((void**)&pAk, g_Ak);
    cudaGetSymbolAddress((void**)&pAv, g_Av);
    cudaGetSymbolAddress((void**)&pWq, g_Wqn);
    cudaGetSymbolAddress((void**)&pWk, g_Wkn);
    cudaGetSymbolAddress((void**)&pWv, g_Wvn);
    cudaGetSymbolAddress((void**)&pWo, g_Won);
    cudaGetSymbolAddress((void**)&pT, g_T);

    const int M = Bb * Ss;       // 4096
    const int N = Hh * DHd;      // 768
    const int Kd = Dd;           // 768

    cudaFuncSetAttribute(hgemm_k,
                         cudaFuncAttributeMaxDynamicSharedMemorySize, GEMM_SMEM);
    cudaFuncSetAttribute(hgemm64_k,
                         cudaFuncAttributeMaxDynamicSharedMemorySize, GEMM64_SMEM);
    cudaFuncSetAttribute(attn_k,
                         cudaFuncAttributeMaxDynamicSharedMemorySize, ATTN_SMEM);

    // Fused init: fp16 conversion + weight transposes + rotary table
    init_k<<<11776, 256>>>(qin, kin, vin, WQ, WK, WV, WO,
                           pAq, pAk, pAv, pWq, pWk, pWv, pWo, pT);

    // Fused QKV projections (Q/K fp16, V fp32 tf32-rounded; head-major)
    hgemm_k<<<dim3(N / 128, M / 128, 3), 256, GEMM_SMEM>>>(
        pAq, pAk, pAv, pWq, pWk, pWv, bQ, bK, bV, pQ, pK, pV, M, N, Kd);

    // Attention (scores fp16 mma, PV tf32; Z fp16)
    attn_k<<<dim3(Ss / 64, Hh, Bb), 256, ATTN_SMEM>>>(pQ, pK, pV, pT, pZ);

    // Output projection (fp16 mma, fp32 out)
    hgemm64_k<<<dim3(N / 64, M / 128), 256, GEMM64_SMEM>>>(
        pZ, pWo, bO, out, M, N, Kd);
}